// round 14
// baseline (speedup 1.0000x reference)
#include <cuda_runtime.h>
#include <cuda_fp16.h>
#include <cstdint>
#include <cstddef>

// ---------------- problem constants ----------------
#define N_HEADS 32
#define D_IN    1408
#define D_HID   256
#define D_OUT   3
#define BATCH   16384

// ---------------- GEMM tiling ----------------
#define M_TILE   128
#define N_TILE   256
#define K_TILE   128                 // fp16 elems -> 256 B per row
#define K_ITERS  (D_IN / K_TILE)     // 11
#define NTHREADS 256                 // 8 warps: 2 (M) x 4 (N), warp tile 64x64

#define NTILES      (BATCH / M_TILE * N_HEADS)   // 4096, tile = head*128 + mtile
#define TILES_PER   28
#define NCTAS       ((NTILES + TILES_PER - 1) / TILES_PER)   // 147

#define ROW_BYTES     256
#define A_STAGE_BYTES (M_TILE * ROW_BYTES)        // 32768
#define B_STAGE_BYTES (N_TILE * ROW_BYTES)        // 65536
#define STAGE_BYTES   (A_STAGE_BYTES + B_STAGE_BYTES)   // 98304

// smem header: DOUBLE-BUFFERED part slices, b1, W2, mbarriers
#define OFF_PART  0        // 2 x 4 x 128 x 3 floats = 12288 B
#define OFF_B1    12288    // 256 floats
#define OFF_W2    13312    // 768 floats
#define OFF_MBAR  16384    // full0, full1, empty0, empty1 (8B each)
#define HDR_BYTES 16448
#define SMEM_SIZE (17408 + 2 * STAGE_BYTES)       // 214016 <= 227KB

// prepass grid split (X convert coarsened x4: each thread does 4 float4)
#define CONV_BLOCKS  ((BATCH * D_IN) / 16 / 256)             // 5632
#define TRANS_BLOCKS (N_HEADS * (D_IN / 32) * (D_HID / 32))  // 11264

// ---------------- device scratch ----------------
__device__ __half g_Xh[(size_t)BATCH * D_IN];                 // 46.1 MB
__device__ __half g_W1h[(size_t)N_HEADS * D_HID * D_IN];      // 23.1 MB (W1^T, K-major)

// ---------------- helpers ----------------
__device__ __forceinline__ uint32_t smem_u32(const void* p) {
    uint32_t a;
    asm("{ .reg .u64 t; cvta.to.shared.u64 t, %1; cvt.u32.u64 %0, t; }" : "=r"(a) : "l"(p));
    return a;
}

__device__ __forceinline__ void cp_async16(uint32_t saddr, const void* gaddr) {
    asm volatile("cp.async.cg.shared.global [%0], [%1], 16;" :: "r"(saddr), "l"(gaddr));
}

__device__ __forceinline__ void cpasync_mbar_arrive_noinc(uint32_t addr) {
    asm volatile("cp.async.mbarrier.arrive.noinc.shared.b64 [%0];" :: "r"(addr) : "memory");
}

__device__ __forceinline__ void mbar_init(uint32_t addr, uint32_t cnt) {
    asm volatile("mbarrier.init.shared.b64 [%0], %1;" :: "r"(addr), "r"(cnt) : "memory");
}

__device__ __forceinline__ void mbar_arrive(uint32_t addr) {
    asm volatile("mbarrier.arrive.shared.b64 _, [%0];" :: "r"(addr) : "memory");
}

__device__ __forceinline__ void mbar_wait(uint32_t addr, uint32_t parity) {
    asm volatile(
        "{\n\t"
        ".reg .pred P;\n\t"
        "WL_%=:\n\t"
        "mbarrier.try_wait.parity.acquire.cta.shared::cta.b64 P, [%0], %1, 0x989680;\n\t"
        "@P bra WD_%=;\n\t"
        "bra WL_%=;\n\t"
        "WD_%=:\n\t"
        "}" :: "r"(addr), "r"(parity) : "memory");
}

__device__ __forceinline__ void ldmatrix_x4(uint32_t* r, uint32_t addr) {
    asm volatile("ldmatrix.sync.aligned.m8n8.x4.shared.b16 {%0,%1,%2,%3}, [%4];"
                 : "=r"(r[0]), "=r"(r[1]), "=r"(r[2]), "=r"(r[3]) : "r"(addr));
}

__device__ __forceinline__ void mma16816(float* c, const uint32_t* a, uint32_t b0, uint32_t b1) {
    asm volatile(
        "mma.sync.aligned.m16n8k16.row.col.f32.f16.f16.f32 "
        "{%0,%1,%2,%3}, {%4,%5,%6,%7}, {%8,%9}, {%0,%1,%2,%3};"
        : "+f"(c[0]), "+f"(c[1]), "+f"(c[2]), "+f"(c[3])
        : "r"(a[0]), "r"(a[1]), "r"(a[2]), "r"(a[3]), "r"(b0), "r"(b1));
}

// ---------------- merged pre-pass: convert X (coarsened x4) + transpose W1 ----------------
__global__ void __launch_bounds__(256)
k_prepass(const float* __restrict__ X, const float* __restrict__ W1) {
    const int tid = threadIdx.x;
    if (blockIdx.x < CONV_BLOCKS) {
        const int i = (blockIdx.x * 256 + tid) * 4;        // four adjacent float4s (MLP=4)
        float4 v[4];
        #pragma unroll
        for (int j = 0; j < 4; j++) v[j] = reinterpret_cast<const float4*>(X)[i + j];
        __half2* o2 = reinterpret_cast<__half2*>(g_Xh);
        #pragma unroll
        for (int j = 0; j < 4; j++) {
            o2[2 * (i + j) + 0] = __floats2half2_rn(v[j].x, v[j].y);
            o2[2 * (i + j) + 1] = __floats2half2_rn(v[j].z, v[j].w);
        }
    } else {
        __shared__ float tile[32][33];
        const int b   = blockIdx.x - CONV_BLOCKS;
        const int h   = b / ((D_IN / 32) * (D_HID / 32));
        const int rem = b % ((D_IN / 32) * (D_HID / 32));
        const int f0  = (rem % (D_IN / 32)) * 32;
        const int o0  = (rem / (D_IN / 32)) * 32;
        const int tx = tid & 31, ty = tid >> 5;     // 32 x 8
        const float* src = W1 + ((size_t)h * D_IN + f0) * D_HID + o0;
        #pragma unroll
        for (int r = 0; r < 32; r += 8)
            tile[ty + r][tx] = src[(size_t)(ty + r) * D_HID + tx];
        __syncthreads();
        __half* dst = g_W1h + ((size_t)h * D_HID + o0) * D_IN + f0;
        #pragma unroll
        for (int r = 0; r < 32; r += 8)
            dst[(size_t)(ty + r) * D_IN + tx] = __float2half_rn(tile[tx][ty + r]);
    }
}

// ---------------- persistent fused GEMM ----------------
// 147 CTAs x up to 28 consecutive tiles. 2-stage mbarrier ring, continuous
// across tiles and tile boundaries (cross-tile fragment prefetch). Slice issue
// at ks 2..4 (empty-wait at ks 2): two extra k-steps of slack for warp skew.
__global__ void __launch_bounds__(NTHREADS, 1)
k_gemm(const float* __restrict__ b1,
       const float* __restrict__ W2,
       const float* __restrict__ b2,
       float* __restrict__ out)
{
    extern __shared__ char smem[];
    float* s_part = (float*)(smem + OFF_PART);   // [2][4][128][3]
    float* s_b1   = (float*)(smem + OFF_B1);
    float* s_W2   = (float*)(smem + OFF_W2);

    const int tid = threadIdx.x;
    const int w   = tid >> 5;
    const int l   = tid & 31;
    const int mw  = w >> 2;
    const int nw  = w & 3;

    int tile       = blockIdx.x * TILES_PER;
    const int tend = min(tile + TILES_PER, NTILES);
    if (tile >= NTILES) return;

    const uint32_t sbase  = smem_u32(smem);
    const uint32_t mb     = sbase + OFF_MBAR;
    const uint32_t tiles0 = (sbase + HDR_BYTES + 1023u) & ~1023u;

    if (tid == 0) {
        mbar_init(mb + 0,  NTHREADS);  // full0
        mbar_init(mb + 8,  NTHREADS);  // full1
        mbar_init(mb + 16, 8);         // empty0
        mbar_init(mb + 24, 8);         // empty1
    }
    {
        const int h0 = tile >> 7;
        for (int i = tid; i < D_HID; i += NTHREADS)      s_b1[i] = b1[h0 * D_HID + i];
        for (int i = tid; i < D_HID * 3; i += NTHREADS)  s_W2[i] = W2[h0 * D_HID * 3 + i];
    }
    __syncthreads();

    const int r16 = tid >> 4;
    const int cc  = tid & 15;
    const uint32_t physoff = (uint32_t)((cc & 7) ^ (r16 & 7)) * 16 + (uint32_t)(cc >> 3) * 128;

    auto tileA = [&](int t) { return g_Xh + (size_t)((t & 127) * M_TILE) * D_IN; };
    auto tileB = [&](int t) { return g_W1h + (size_t)((t >> 7) * D_HID) * D_IN; };

    auto issue_slice = [&](int slot, const __half* gA, const __half* gB, int k0, int slice) {
        const uint32_t st = tiles0 + slot * STAGE_BYTES;
        if (slice < 2) {
            #pragma unroll
            for (int j = 0; j < 4; j++) {
                const int row = (slice * 4 + j) * 16 + r16;
                cp_async16(st + row * ROW_BYTES + physoff,
                           gA + (size_t)row * D_IN + k0 + cc * 8);
            }
        } else {
            #pragma unroll
            for (int j = 0; j < 4; j++) {
                const int row = ((slice - 2) * 4 + j) * 16 + r16;
                cp_async16(st + A_STAGE_BYTES + row * ROW_BYTES + physoff,
                           gB + (size_t)row * D_IN + k0 + cc * 8);
            }
        }
    };

    float acc[4][8][4];
    #pragma unroll
    for (int mi = 0; mi < 4; mi++)
        #pragma unroll
        for (int ni = 0; ni < 8; ni++)
            #pragma unroll
            for (int t = 0; t < 4; t++) acc[mi][ni][t] = 0.0f;

    const int a_row_in16 = l & 15;
    const int a_cadd     = l >> 4;
    const int b_row_in16 = ((l >> 4) << 3) + (l & 7);
    const int b_cadd     = (l >> 3) & 1;

    uint32_t af[2][4][4];
    uint32_t bf[2][4][4];

    auto load_frags = [&](int buf, uint32_t stA, uint32_t stB, int ks) {
        #pragma unroll
        for (int mi = 0; mi < 4; mi++) {
            const int row = mw * 64 + mi * 16 + a_row_in16;
            const int ch  = ks * 2 + a_cadd;
            ldmatrix_x4(af[buf][mi],
                stA + row * ROW_BYTES + ((uint32_t)(ch >> 3) << 7)
                    + ((uint32_t)((ch & 7) ^ (row & 7)) << 4));
        }
        #pragma unroll
        for (int nj = 0; nj < 4; nj++) {
            const int row = nw * 64 + nj * 16 + b_row_in16;
            const int ch  = ks * 2 + b_cadd;
            ldmatrix_x4(bf[buf][nj],
                stB + row * ROW_BYTES + ((uint32_t)(ch >> 3) << 7)
                    + ((uint32_t)((ch & 7) ^ (row & 7)) << 4));
        }
    };

    auto do_mmas = [&](int buf) {
        #pragma unroll
        for (int mi = 0; mi < 4; mi++)
            #pragma unroll
            for (int nj = 0; nj < 4; nj++) {
                mma16816(acc[mi][2 * nj],     af[buf][mi], bf[buf][nj][0], bf[buf][nj][1]);
                mma16816(acc[mi][2 * nj + 1], af[buf][mi], bf[buf][nj][2], bf[buf][nj][3]);
            }
    };

    // prologue: fill stage 0 with (tile, k=0)
    {
        const __half* gA = tileA(tile);
        const __half* gB = tileB(tile);
        #pragma unroll
        for (int s = 0; s < 6; s++) issue_slice(0, gA, gB, 0, s);
        cpasync_mbar_arrive_noinc(mb + 0);
    }

    int g = 0;
    for (; tile < tend; tile++) {
        const __half* gA_cur = tileA(tile);
        const __half* gB_cur = tileB(tile);
        const bool    has_nxt = (tile + 1 < tend);
        const __half* gA_nxt = has_nxt ? tileA(tile + 1) : gA_cur;
        const __half* gB_nxt = has_nxt ? tileB(tile + 1) : gB_cur;

        for (int kk = 0; kk < K_ITERS; kk++, g++) {
            const int s = g & 1;
            const uint32_t stA = tiles0 + s * STAGE_BYTES;
            const uint32_t stB = stA + A_STAGE_BYTES;

            if (g == 0) {                        // only the CTA's very first iteration
                mbar_wait(mb + s * 8, 0);
                load_frags(0, stA, stB, 0);
            }

            // next iteration's data source (cross-tile at kk==10)
            const bool    valid = (kk < K_ITERS - 1) || has_nxt;
            const __half* iA = (kk < K_ITERS - 1) ? gA_cur : gA_nxt;
            const __half* iB = (kk < K_ITERS - 1) ? gB_cur : gB_nxt;
            const int     ik0 = (kk < K_ITERS - 1) ? (kk + 1) * K_TILE : 0;
            const int     nslot = (g + 1) & 1;
            const uint32_t nA = tiles0 + nslot * STAGE_BYTES;

            #pragma unroll
            for (int ks = 0; ks < 8; ks++) {
                do_mmas(ks & 1);                         // HMMA first: frags ready
                if (ks >= 2 && ks <= 4 && valid) {       // slices at ks 2..4 (more skew slack)
                    if (ks == 2 && g >= 1)
                        mbar_wait(mb + 16 + nslot * 8, ((g - 1) >> 1) & 1);
                    issue_slice(nslot, iA, iB, ik0, 2 * (ks - 2));
                    issue_slice(nslot, iA, iB, ik0, 2 * (ks - 2) + 1);
                    if (ks == 4) cpasync_mbar_arrive_noinc(mb + nslot * 8);
                }
                if (ks < 7) {
                    load_frags((ks + 1) & 1, stA, stB, ks + 1);
                } else if (valid) {                      // cross-stage AND cross-tile prefetch
                    mbar_wait(mb + nslot * 8, ((g + 1) >> 1) & 1);
                    load_frags(0, nA, nA + A_STAGE_BYTES, 0);
                }
            }
            if (l == 0) mbar_arrive(mb + 16 + s * 8);    // empty[s]
        }

        // -------- per-tile epilogue (atomic-free, double-buffered, one sync) --------
        float* sp_base = s_part + (tile & 1) * (4 * M_TILE * 3);

        float part[8][3];
        #pragma unroll
        for (int r = 0; r < 8; r++) { part[r][0] = part[r][1] = part[r][2] = 0.0f; }

        #pragma unroll
        for (int mi = 0; mi < 4; mi++)
            #pragma unroll
            for (int ni = 0; ni < 8; ni++)
                #pragma unroll
                for (int t2 = 0; t2 < 4; t2++) {
                    const int q = t2 >> 1, t = t2 & 1;
                    const int n = nw * 64 + ni * 8 + (l & 3) * 2 + t;
                    float h = acc[mi][ni][t2] + s_b1[n];
                    acc[mi][ni][t2] = 0.0f;
                    h = fmaxf(h, 0.0f);
                    part[mi * 2 + q][0] = fmaf(h, s_W2[n * 3 + 0], part[mi * 2 + q][0]);
                    part[mi * 2 + q][1] = fmaf(h, s_W2[n * 3 + 1], part[mi * 2 + q][1]);
                    part[mi * 2 + q][2] = fmaf(h, s_W2[n * 3 + 2], part[mi * 2 + q][2]);
                }

        #pragma unroll
        for (int r = 0; r < 8; r++)
            #pragma unroll
            for (int p = 0; p < 3; p++) {
                part[r][p] += __shfl_xor_sync(0xffffffffu, part[r][p], 1);
                part[r][p] += __shfl_xor_sync(0xffffffffu, part[r][p], 2);
            }

        if ((l & 3) == 0) {
            #pragma unroll
            for (int mi = 0; mi < 4; mi++)
                #pragma unroll
                for (int q = 0; q < 2; q++) {
                    const int row = mw * 64 + mi * 16 + (l >> 2) + q * 8;
                    float* sp = sp_base + (nw * M_TILE + row) * 3;
                    sp[0] = part[mi * 2 + q][0];
                    sp[1] = part[mi * 2 + q][1];
                    sp[2] = part[mi * 2 + q][2];
                }
        }
        __syncthreads();     // S1: part slices + prior-tile read ordering

        if (has_nxt && ((tile + 1) >> 7) != (tile >> 7)) {   // rare: head change
            const int nh = (tile + 1) >> 7;
            for (int i = tid; i < D_HID; i += NTHREADS)     s_b1[i] = b1[nh * D_HID + i];
            for (int i = tid; i < D_HID * 3; i += NTHREADS) s_W2[i] = W2[nh * D_HID * 3 + i];
            __syncthreads();   // header visible before next tile's epilogue reads
        }

        if (tid < M_TILE) {
            const int mt = tile & 127, hd = tile >> 7;
            const float* sp = sp_base + tid * 3;
            float o0 = sp[0] + sp[384] + sp[768] + sp[1152];
            float o1 = sp[1] + sp[385] + sp[769] + sp[1153];
            float o2 = sp[2] + sp[386] + sp[770] + sp[1154];
            float* po = out + (size_t)(mt * M_TILE + tid) * (N_HEADS * D_OUT) + hd * 3;
            po[0] = o0 + __ldg(&b2[hd * 3 + 0]);
            po[1] = o1 + __ldg(&b2[hd * 3 + 1]);
            po[2] = o2 + __ldg(&b2[hd * 3 + 2]);
        }
        // no trailing sync: next tile writes the OTHER s_part buffer; reads of this
        // buffer complete before the next S1, which orders them vs. tile+2 writes.
    }
}

// ---------------- host launch ----------------
extern "C" void kernel_launch(void* const* d_in, const int* in_sizes, int n_in,
                              void* d_out, int out_size) {
    const float* X  = (const float*)d_in[0];
    const float* W1 = (const float*)d_in[1];
    const float* b1 = (const float*)d_in[2];
    const float* W2 = (const float*)d_in[3];
    const float* b2 = (const float*)d_in[4];
    float* out = (float*)d_out;
    (void)in_sizes; (void)n_in; (void)out_size;

    k_prepass<<<CONV_BLOCKS + TRANS_BLOCKS, 256>>>(X, W1);

    static bool attr_set = false;
    if (!attr_set) {
        cudaFuncSetAttribute(k_gemm, cudaFuncAttributeMaxDynamicSharedMemorySize, SMEM_SIZE);
        attr_set = true;
    }
    k_gemm<<<NCTAS, NTHREADS, SMEM_SIZE>>>(b1, W2, b2, out);
}

// round 15
// speedup vs baseline: 1.0801x; 1.0801x over previous
#include <cuda_runtime.h>
#include <cuda_fp16.h>
#include <cstdint>
#include <cstddef>

// ---------------- problem constants ----------------
#define N_HEADS 32
#define D_IN    1408
#define D_HID   256
#define D_OUT   3
#define BATCH   16384

// ---------------- GEMM tiling ----------------
#define M_TILE   128
#define N_TILE   256
#define K_TILE   128                 // fp16 elems -> 256 B per row
#define K_ITERS  (D_IN / K_TILE)     // 11
#define NTHREADS 256                 // 8 warps: 2 (M) x 4 (N), warp tile 64x64

#define NTILES      (BATCH / M_TILE * N_HEADS)   // 4096, tile = head*128 + mtile
#define TILES_PER   28
#define NCTAS       ((NTILES + TILES_PER - 1) / TILES_PER)   // 147

#define ROW_BYTES     256
#define A_STAGE_BYTES (M_TILE * ROW_BYTES)        // 32768
#define B_STAGE_BYTES (N_TILE * ROW_BYTES)        // 65536
#define STAGE_BYTES   (A_STAGE_BYTES + B_STAGE_BYTES)   // 98304

// smem header: DOUBLE-BUFFERED part slices, b1, W2, mbarriers
#define OFF_PART  0        // 2 x 4 x 128 x 3 floats = 12288 B
#define OFF_B1    12288    // 256 floats
#define OFF_W2    13312    // 768 floats
#define OFF_MBAR  16384    // full0, full1, empty0, empty1 (8B each)
#define HDR_BYTES 16448
#define SMEM_SIZE (17408 + 2 * STAGE_BYTES)       // 214016 <= 227KB

// prepass grid split (X convert coarsened x2: each thread does 2 float4)
#define CONV_BLOCKS  ((BATCH * D_IN) / 8 / 256)              // 11264
#define TRANS_BLOCKS (N_HEADS * (D_IN / 32) * (D_HID / 32))  // 11264

// ---------------- device scratch ----------------
__device__ __half g_Xh[(size_t)BATCH * D_IN];                 // 46.1 MB
__device__ __half g_W1h[(size_t)N_HEADS * D_HID * D_IN];      // 23.1 MB (W1^T, K-major)

// ---------------- helpers ----------------
__device__ __forceinline__ uint32_t smem_u32(const void* p) {
    uint32_t a;
    asm("{ .reg .u64 t; cvta.to.shared.u64 t, %1; cvt.u32.u64 %0, t; }" : "=r"(a) : "l"(p));
    return a;
}

__device__ __forceinline__ void cp_async16(uint32_t saddr, const void* gaddr) {
    asm volatile("cp.async.cg.shared.global [%0], [%1], 16;" :: "r"(saddr), "l"(gaddr));
}

__device__ __forceinline__ void cpasync_mbar_arrive_noinc(uint32_t addr) {
    asm volatile("cp.async.mbarrier.arrive.noinc.shared.b64 [%0];" :: "r"(addr) : "memory");
}

__device__ __forceinline__ void mbar_init(uint32_t addr, uint32_t cnt) {
    asm volatile("mbarrier.init.shared.b64 [%0], %1;" :: "r"(addr), "r"(cnt) : "memory");
}

__device__ __forceinline__ void mbar_arrive(uint32_t addr) {
    asm volatile("mbarrier.arrive.shared.b64 _, [%0];" :: "r"(addr) : "memory");
}

__device__ __forceinline__ void mbar_wait(uint32_t addr, uint32_t parity) {
    asm volatile(
        "{\n\t"
        ".reg .pred P;\n\t"
        "WL_%=:\n\t"
        "mbarrier.try_wait.parity.acquire.cta.shared::cta.b64 P, [%0], %1, 0x989680;\n\t"
        "@P bra WD_%=;\n\t"
        "bra WL_%=;\n\t"
        "WD_%=:\n\t"
        "}" :: "r"(addr), "r"(parity) : "memory");
}

__device__ __forceinline__ void ldmatrix_x4(uint32_t* r, uint32_t addr) {
    asm volatile("ldmatrix.sync.aligned.m8n8.x4.shared.b16 {%0,%1,%2,%3}, [%4];"
                 : "=r"(r[0]), "=r"(r[1]), "=r"(r[2]), "=r"(r[3]) : "r"(addr));
}

__device__ __forceinline__ void mma16816(float* c, const uint32_t* a, uint32_t b0, uint32_t b1) {
    asm volatile(
        "mma.sync.aligned.m16n8k16.row.col.f32.f16.f16.f32 "
        "{%0,%1,%2,%3}, {%4,%5,%6,%7}, {%8,%9}, {%0,%1,%2,%3};"
        : "+f"(c[0]), "+f"(c[1]), "+f"(c[2]), "+f"(c[3])
        : "r"(a[0]), "r"(a[1]), "r"(a[2]), "r"(a[3]), "r"(b0), "r"(b1));
}

// ---------------- merged pre-pass: convert X (coarsened x2) + transpose W1 ----------------
__global__ void __launch_bounds__(256)
k_prepass(const float* __restrict__ X, const float* __restrict__ W1) {
    const int tid = threadIdx.x;
    if (blockIdx.x < CONV_BLOCKS) {
        const int i = (blockIdx.x * 256 + tid) * 2;        // two adjacent float4s
        const float4 v0 = reinterpret_cast<const float4*>(X)[i];
        const float4 v1 = reinterpret_cast<const float4*>(X)[i + 1];
        __half2* o2 = reinterpret_cast<__half2*>(g_Xh);
        o2[2 * i + 0] = __floats2half2_rn(v0.x, v0.y);
        o2[2 * i + 1] = __floats2half2_rn(v0.z, v0.w);
        o2[2 * i + 2] = __floats2half2_rn(v1.x, v1.y);
        o2[2 * i + 3] = __floats2half2_rn(v1.z, v1.w);
    } else {
        __shared__ float tile[32][33];
        const int b   = blockIdx.x - CONV_BLOCKS;
        const int h   = b / ((D_IN / 32) * (D_HID / 32));
        const int rem = b % ((D_IN / 32) * (D_HID / 32));
        const int f0  = (rem % (D_IN / 32)) * 32;
        const int o0  = (rem / (D_IN / 32)) * 32;
        const int tx = tid & 31, ty = tid >> 5;     // 32 x 8
        const float* src = W1 + ((size_t)h * D_IN + f0) * D_HID + o0;
        #pragma unroll
        for (int r = 0; r < 32; r += 8)
            tile[ty + r][tx] = src[(size_t)(ty + r) * D_HID + tx];
        __syncthreads();
        __half* dst = g_W1h + ((size_t)h * D_HID + o0) * D_IN + f0;
        #pragma unroll
        for (int r = 0; r < 32; r += 8)
            dst[(size_t)(ty + r) * D_IN + tx] = __float2half_rn(tile[tx][ty + r]);
    }
}

// ---------------- persistent fused GEMM ----------------
// 147 CTAs x up to 28 consecutive tiles. 2-stage mbarrier ring, continuous
// across tiles and tile boundaries (cross-tile fragment prefetch). Slice issue
// at ks 1..3 (empty-wait at ks 1): measured optimum of skew-slack vs landing-slack.
__global__ void __launch_bounds__(NTHREADS, 1)
k_gemm(const float* __restrict__ b1,
       const float* __restrict__ W2,
       const float* __restrict__ b2,
       float* __restrict__ out)
{
    extern __shared__ char smem[];
    float* s_part = (float*)(smem + OFF_PART);   // [2][4][128][3]
    float* s_b1   = (float*)(smem + OFF_B1);
    float* s_W2   = (float*)(smem + OFF_W2);

    const int tid = threadIdx.x;
    const int w   = tid >> 5;
    const int l   = tid & 31;
    const int mw  = w >> 2;
    const int nw  = w & 3;

    int tile       = blockIdx.x * TILES_PER;
    const int tend = min(tile + TILES_PER, NTILES);
    if (tile >= NTILES) return;

    const uint32_t sbase  = smem_u32(smem);
    const uint32_t mb     = sbase + OFF_MBAR;
    const uint32_t tiles0 = (sbase + HDR_BYTES + 1023u) & ~1023u;

    if (tid == 0) {
        mbar_init(mb + 0,  NTHREADS);  // full0
        mbar_init(mb + 8,  NTHREADS);  // full1
        mbar_init(mb + 16, 8);         // empty0
        mbar_init(mb + 24, 8);         // empty1
    }
    {
        const int h0 = tile >> 7;
        for (int i = tid; i < D_HID; i += NTHREADS)      s_b1[i] = b1[h0 * D_HID + i];
        for (int i = tid; i < D_HID * 3; i += NTHREADS)  s_W2[i] = W2[h0 * D_HID * 3 + i];
    }
    __syncthreads();

    const int r16 = tid >> 4;
    const int cc  = tid & 15;
    const uint32_t physoff = (uint32_t)((cc & 7) ^ (r16 & 7)) * 16 + (uint32_t)(cc >> 3) * 128;

    auto tileA = [&](int t) { return g_Xh + (size_t)((t & 127) * M_TILE) * D_IN; };
    auto tileB = [&](int t) { return g_W1h + (size_t)((t >> 7) * D_HID) * D_IN; };

    auto issue_slice = [&](int slot, const __half* gA, const __half* gB, int k0, int slice) {
        const uint32_t st = tiles0 + slot * STAGE_BYTES;
        if (slice < 2) {
            #pragma unroll
            for (int j = 0; j < 4; j++) {
                const int row = (slice * 4 + j) * 16 + r16;
                cp_async16(st + row * ROW_BYTES + physoff,
                           gA + (size_t)row * D_IN + k0 + cc * 8);
            }
        } else {
            #pragma unroll
            for (int j = 0; j < 4; j++) {
                const int row = ((slice - 2) * 4 + j) * 16 + r16;
                cp_async16(st + A_STAGE_BYTES + row * ROW_BYTES + physoff,
                           gB + (size_t)row * D_IN + k0 + cc * 8);
            }
        }
    };

    float acc[4][8][4];
    #pragma unroll
    for (int mi = 0; mi < 4; mi++)
        #pragma unroll
        for (int ni = 0; ni < 8; ni++)
            #pragma unroll
            for (int t = 0; t < 4; t++) acc[mi][ni][t] = 0.0f;

    const int a_row_in16 = l & 15;
    const int a_cadd     = l >> 4;
    const int b_row_in16 = ((l >> 4) << 3) + (l & 7);
    const int b_cadd     = (l >> 3) & 1;

    uint32_t af[2][4][4];
    uint32_t bf[2][4][4];

    auto load_frags = [&](int buf, uint32_t stA, uint32_t stB, int ks) {
        #pragma unroll
        for (int mi = 0; mi < 4; mi++) {
            const int row = mw * 64 + mi * 16 + a_row_in16;
            const int ch  = ks * 2 + a_cadd;
            ldmatrix_x4(af[buf][mi],
                stA + row * ROW_BYTES + ((uint32_t)(ch >> 3) << 7)
                    + ((uint32_t)((ch & 7) ^ (row & 7)) << 4));
        }
        #pragma unroll
        for (int nj = 0; nj < 4; nj++) {
            const int row = nw * 64 + nj * 16 + b_row_in16;
            const int ch  = ks * 2 + b_cadd;
            ldmatrix_x4(bf[buf][nj],
                stB + row * ROW_BYTES + ((uint32_t)(ch >> 3) << 7)
                    + ((uint32_t)((ch & 7) ^ (row & 7)) << 4));
        }
    };

    auto do_mmas = [&](int buf) {
        #pragma unroll
        for (int mi = 0; mi < 4; mi++)
            #pragma unroll
            for (int nj = 0; nj < 4; nj++) {
                mma16816(acc[mi][2 * nj],     af[buf][mi], bf[buf][nj][0], bf[buf][nj][1]);
                mma16816(acc[mi][2 * nj + 1], af[buf][mi], bf[buf][nj][2], bf[buf][nj][3]);
            }
    };

    // prologue: fill stage 0 with (tile, k=0)
    {
        const __half* gA = tileA(tile);
        const __half* gB = tileB(tile);
        #pragma unroll
        for (int s = 0; s < 6; s++) issue_slice(0, gA, gB, 0, s);
        cpasync_mbar_arrive_noinc(mb + 0);
    }

    int g = 0;
    for (; tile < tend; tile++) {
        const __half* gA_cur = tileA(tile);
        const __half* gB_cur = tileB(tile);
        const bool    has_nxt = (tile + 1 < tend);
        const __half* gA_nxt = has_nxt ? tileA(tile + 1) : gA_cur;
        const __half* gB_nxt = has_nxt ? tileB(tile + 1) : gB_cur;

        for (int kk = 0; kk < K_ITERS; kk++, g++) {
            const int s = g & 1;
            const uint32_t stA = tiles0 + s * STAGE_BYTES;
            const uint32_t stB = stA + A_STAGE_BYTES;

            if (g == 0) {                        // only the CTA's very first iteration
                mbar_wait(mb + s * 8, 0);
                load_frags(0, stA, stB, 0);
            }

            // next iteration's data source (cross-tile at kk==10)
            const bool    valid = (kk < K_ITERS - 1) || has_nxt;
            const __half* iA = (kk < K_ITERS - 1) ? gA_cur : gA_nxt;
            const __half* iB = (kk < K_ITERS - 1) ? gB_cur : gB_nxt;
            const int     ik0 = (kk < K_ITERS - 1) ? (kk + 1) * K_TILE : 0;
            const int     nslot = (g + 1) & 1;
            const uint32_t nA = tiles0 + nslot * STAGE_BYTES;

            #pragma unroll
            for (int ks = 0; ks < 8; ks++) {
                do_mmas(ks & 1);                         // HMMA first: frags ready
                if (ks >= 1 && ks <= 3 && valid) {       // slices at ks 1..3 (optimum)
                    if (ks == 1 && g >= 1)
                        mbar_wait(mb + 16 + nslot * 8, ((g - 1) >> 1) & 1);
                    issue_slice(nslot, iA, iB, ik0, 2 * (ks - 1));
                    issue_slice(nslot, iA, iB, ik0, 2 * (ks - 1) + 1);
                    if (ks == 3) cpasync_mbar_arrive_noinc(mb + nslot * 8);
                }
                if (ks < 7) {
                    load_frags((ks + 1) & 1, stA, stB, ks + 1);
                } else if (valid) {                      // cross-stage AND cross-tile prefetch
                    mbar_wait(mb + nslot * 8, ((g + 1) >> 1) & 1);
                    load_frags(0, nA, nA + A_STAGE_BYTES, 0);
                }
            }
            if (l == 0) mbar_arrive(mb + 16 + s * 8);    // empty[s]
        }

        // -------- per-tile epilogue (atomic-free, double-buffered, one sync) --------
        float* sp_base = s_part + (tile & 1) * (4 * M_TILE * 3);

        float part[8][3];
        #pragma unroll
        for (int r = 0; r < 8; r++) { part[r][0] = part[r][1] = part[r][2] = 0.0f; }

        #pragma unroll
        for (int mi = 0; mi < 4; mi++)
            #pragma unroll
            for (int ni = 0; ni < 8; ni++)
                #pragma unroll
                for (int t2 = 0; t2 < 4; t2++) {
                    const int q = t2 >> 1, t = t2 & 1;
                    const int n = nw * 64 + ni * 8 + (l & 3) * 2 + t;
                    float h = acc[mi][ni][t2] + s_b1[n];
                    acc[mi][ni][t2] = 0.0f;
                    h = fmaxf(h, 0.0f);
                    part[mi * 2 + q][0] = fmaf(h, s_W2[n * 3 + 0], part[mi * 2 + q][0]);
                    part[mi * 2 + q][1] = fmaf(h, s_W2[n * 3 + 1], part[mi * 2 + q][1]);
                    part[mi * 2 + q][2] = fmaf(h, s_W2[n * 3 + 2], part[mi * 2 + q][2]);
                }

        #pragma unroll
        for (int r = 0; r < 8; r++)
            #pragma unroll
            for (int p = 0; p < 3; p++) {
                part[r][p] += __shfl_xor_sync(0xffffffffu, part[r][p], 1);
                part[r][p] += __shfl_xor_sync(0xffffffffu, part[r][p], 2);
            }

        if ((l & 3) == 0) {
            #pragma unroll
            for (int mi = 0; mi < 4; mi++)
                #pragma unroll
                for (int q = 0; q < 2; q++) {
                    const int row = mw * 64 + mi * 16 + (l >> 2) + q * 8;
                    float* sp = sp_base + (nw * M_TILE + row) * 3;
                    sp[0] = part[mi * 2 + q][0];
                    sp[1] = part[mi * 2 + q][1];
                    sp[2] = part[mi * 2 + q][2];
                }
        }
        __syncthreads();     // S1: part slices + prior-tile read ordering

        if (has_nxt && ((tile + 1) >> 7) != (tile >> 7)) {   // rare: head change
            const int nh = (tile + 1) >> 7;
            for (int i = tid; i < D_HID; i += NTHREADS)     s_b1[i] = b1[nh * D_HID + i];
            for (int i = tid; i < D_HID * 3; i += NTHREADS) s_W2[i] = W2[nh * D_HID * 3 + i];
            __syncthreads();   // header visible before next tile's epilogue reads
        }

        if (tid < M_TILE) {
            const int mt = tile & 127, hd = tile >> 7;
            const float* sp = sp_base + tid * 3;
            float o0 = sp[0] + sp[384] + sp[768] + sp[1152];
            float o1 = sp[1] + sp[385] + sp[769] + sp[1153];
            float o2 = sp[2] + sp[386] + sp[770] + sp[1154];
            float* po = out + (size_t)(mt * M_TILE + tid) * (N_HEADS * D_OUT) + hd * 3;
            po[0] = o0 + __ldg(&b2[hd * 3 + 0]);
            po[1] = o1 + __ldg(&b2[hd * 3 + 1]);
            po[2] = o2 + __ldg(&b2[hd * 3 + 2]);
        }
        // no trailing sync: next tile writes the OTHER s_part buffer; reads of this
        // buffer complete before the next S1, which orders them vs. tile+2 writes.
    }
}

// ---------------- host launch ----------------
extern "C" void kernel_launch(void* const* d_in, const int* in_sizes, int n_in,
                              void* d_out, int out_size) {
    const float* X  = (const float*)d_in[0];
    const float* W1 = (const float*)d_in[1];
    const float* b1 = (const float*)d_in[2];
    const float* W2 = (const float*)d_in[3];
    const float* b2 = (const float*)d_in[4];
    float* out = (float*)d_out;
    (void)in_sizes; (void)n_in; (void)out_size;

    k_prepass<<<CONV_BLOCKS + TRANS_BLOCKS, 256>>>(X, W1);

    static bool attr_set = false;
    if (!attr_set) {
        cudaFuncSetAttribute(k_gemm, cudaFuncAttributeMaxDynamicSharedMemorySize, SMEM_SIZE);
        attr_set = true;
    }
    k_gemm<<<NCTAS, NTHREADS, SMEM_SIZE>>>(b1, W2, b2, out);
}